// round 1
// baseline (speedup 1.0000x reference)
#include <cuda_runtime.h>

#define BB 32
#define TT 36
#define NN 10000
#define FF 3
#define HH 10
#define RR 20

// ---- scratch (no allocations allowed) ----
__device__ float g_tm[BB * NN];        // time_mean[b][n]
__device__ float g_rsum[BB * RR];      // per (b, region) sum of valid means
__device__ float g_rcnt[BB * RR];      // per (b, region) count of valid means
__device__ float g_g1;                 // global nanmean of pred_speed
__device__ int   g_is64;               // cluster_id stored as int64?

// ---------------------------------------------------------------------------
// Kernel 0: zero accumulators + detect cluster_id dtype (int32 vs int64-LE).
// If int64: odd int32 words of the first 10000 words are all zero (values 0..19).
// If int32: odd words are random region ids (only ~5% are zero).
// Reading the first 10000 int32 words is in-bounds for both interpretations.
// ---------------------------------------------------------------------------
__global__ void k_init(const int* __restrict__ cid32) {
    int tid = threadIdx.x;
    for (int i = tid; i < BB * RR; i += blockDim.x) {
        g_rsum[i] = 0.0f;
        g_rcnt[i] = 0.0f;
    }
    int zc = 0;
    for (int i = tid; i < NN / 2; i += blockDim.x)
        if (cid32[2 * i + 1] == 0) zc++;
    __shared__ int s_z;
    if (tid == 0) s_z = 0;
    __syncthreads();
    atomicAdd(&s_z, zc);
    __syncthreads();
    if (tid == 0) g_is64 = (s_z > 4000) ? 1 : 0;
}

// ---------------------------------------------------------------------------
// Kernel 1: per (b, n) NaN-aware mean over T, + region partial sums.
// grid: (ceil(N/256), B), block: 256
// ---------------------------------------------------------------------------
__global__ void k_mean(const float* __restrict__ seq, const int* __restrict__ cid32) {
    const int n = blockIdx.x * blockDim.x + threadIdx.x;
    const int b = blockIdx.y;

    __shared__ float srs[RR];
    __shared__ float src[RR];
    if (threadIdx.x < RR) { srs[threadIdx.x] = 0.0f; src[threadIdx.x] = 0.0f; }
    __syncthreads();

    if (n < NN) {
        const float* p = seq + ((size_t)b * TT * NN + (size_t)n) * FF;
        float s = 0.0f, c = 0.0f;
#pragma unroll
        for (int t = 0; t < TT; t++) {
            float v = p[(size_t)t * NN * FF];
            if (v == v) { s += v; c += 1.0f; }
        }
        float tm = s / c;                 // c==0 -> 0/0 -> NaN (all-NaN node)
        g_tm[b * NN + n] = tm;
        if (c > 0.0f) {
            int r = g_is64 ? cid32[2 * n] : cid32[n];
            atomicAdd(&srs[r], tm);
            atomicAdd(&src[r], 1.0f);
        }
    }
    __syncthreads();
    if (threadIdx.x < RR && src[threadIdx.x] > 0.0f) {
        atomicAdd(&g_rsum[b * RR + threadIdx.x], srs[threadIdx.x]);
        atomicAdd(&g_rcnt[b * RR + threadIdx.x], src[threadIdx.x]);
    }
}

// ---------------------------------------------------------------------------
// Kernel 2: one block, 640 threads = (b, r) pairs.
// Computes g1 (global nanmean of pred_speed == weighted mean of all region sums),
// regional means, g2 (nanmean over regional), writes out_regional with NaN->g2,
// stores g1 for kernel 3.
// ---------------------------------------------------------------------------
__global__ void k_regional(float* __restrict__ out) {
    const int tid = threadIdx.x;          // 0..639
    float rs = g_rsum[tid];
    float rc = g_rcnt[tid];

    __shared__ float s_gs, s_gc, s_2s, s_2c;
    if (tid == 0) { s_gs = 0.0f; s_gc = 0.0f; s_2s = 0.0f; s_2c = 0.0f; }
    __syncthreads();

    atomicAdd(&s_gs, rs);
    atomicAdd(&s_gc, rc);
    float reg = rs / rc;                  // NaN if region all-NaN for this b
    if (rc > 0.0f) { atomicAdd(&s_2s, reg); atomicAdd(&s_2c, 1.0f); }
    __syncthreads();

    if (tid == 0) g_g1 = s_gs / s_gc;
    float g2 = s_2s / s_2c;
    float val = (rc > 0.0f) ? reg : g2;

    const int b = tid / RR;
    const int r = tid % RR;
    float* o = out + (size_t)BB * HH * NN;
#pragma unroll
    for (int h = 0; h < HH; h++)
        o[(b * HH + h) * RR + r] = val;
}

// ---------------------------------------------------------------------------
// Kernel 3: write out_pred [B, 10, N] = tiled time_mean with NaN -> g1.
// float4 vectorized (N % 4 == 0). g_tm re-reads hit L2.
// ---------------------------------------------------------------------------
__global__ void k_pred(float* __restrict__ out) {
    const int total4 = BB * HH * NN / 4;
    int i = blockIdx.x * blockDim.x + threadIdx.x;
    if (i >= total4) return;
    int flat = i * 4;
    int n  = flat % NN;
    int bh = flat / NN;
    int b  = bh / HH;

    float4 v = *reinterpret_cast<const float4*>(&g_tm[b * NN + n]);
    float g1 = g_g1;
    if (!(v.x == v.x)) v.x = g1;
    if (!(v.y == v.y)) v.y = g1;
    if (!(v.z == v.z)) v.z = g1;
    if (!(v.w == v.w)) v.w = g1;
    *reinterpret_cast<float4*>(&out[flat]) = v;
}

// ---------------------------------------------------------------------------
extern "C" void kernel_launch(void* const* d_in, const int* in_sizes, int n_in,
                              void* d_out, int out_size) {
    const float* seq   = (const float*)d_in[0];
    const int*   cid32 = (const int*)d_in[1];   // int32 or int64 (detected on device)
    float*       out   = (float*)d_out;

    k_init<<<1, 256>>>(cid32);

    dim3 gridA((NN + 255) / 256, BB);
    k_mean<<<gridA, 256>>>(seq, cid32);

    k_regional<<<1, BB * RR>>>(out);

    int total4 = BB * HH * NN / 4;
    k_pred<<<(total4 + 255) / 256, 256>>>(out);
}